// round 10
// baseline (speedup 1.0000x reference)
#include <cuda_runtime.h>
#include <cuda_fp16.h>
#include <cstdint>

// ============================================================
// out[b,k,c] = softmax_m( tanh(e[b,m]·W1[k] + d[b,k]·W2[m]) ) · x[b,m,c]
// B=16, N=2048, D=128.
// Flash-style fused attention, mma.sync.m16n8k16 + ldmatrix + cp.async.
// tanh bounds scores in [-1,1] -> no online max rescaling needed.
// R9: (a) full f16x2 weight path (cvt+tanh+fma+ex2, 2 MUFU / 2 weights),
//     (b) denominator accumulated via ones-MMA from the same Pf fragments
//     (exact num/den weight consistency, no epilogue shuffle reduce).
// ============================================================

#define DEVI __device__ __forceinline__

constexpr int B_ = 16, N_ = 2048, D_ = 128, F_ = 256;
constexpr int MT = 256;              // queries per CTA
constexpr int KT = 64;               // keys per chunk
constexpr int NCHUNK = N_ / KT;      // 32

constexpr uint32_t ONES_H2 = 0x3C003C00u;   // half2(1.0, 1.0)

// ---------------- device scratch -------------------------------------------
__device__ __half g_Qf[(size_t)B_ * N_ * F_];   // [b,k,256] = [W1[k] | d[b,k]]
__device__ __half g_Kf[(size_t)B_ * N_ * F_];   // [b,m,256] = [e[b,m] | W2[m]]
__device__ __half g_XT[(size_t)B_ * D_ * N_];   // [b,c,m]   = x[b,m,c]

// ---------------- SMEM layout (bytes), XOR-swizzled, no padding -------------
constexpr int SM_Q   = 0;
constexpr int QSIZE  = MT * 512;                // 131072
constexpr int KSTAGE = KT * 512;                // 32768
constexpr int SM_K   = SM_Q + QSIZE;
constexpr int XSTAGE = D_ * 128;                // 16384
constexpr int SM_X   = SM_K + 2 * KSTAGE;
constexpr int SMEM_TOTAL = SM_X + 2 * XSTAGE;   // 229376 (224 KB)

// ---------------- PTX helpers ----------------------------------------------
DEVI uint32_t smem_u32(const void* p) {
    uint32_t a;
    asm("{ .reg .u64 t; cvta.to.shared.u64 t, %1; cvt.u32.u64 %0, t; }" : "=r"(a) : "l"(p));
    return a;
}

DEVI void cp_async16(uint32_t dst, const void* src) {
    asm volatile("cp.async.cg.shared.global [%0], [%1], 16;" :: "r"(dst), "l"(src) : "memory");
}
DEVI void cp_commit() { asm volatile("cp.async.commit_group;" ::: "memory"); }
DEVI void cp_wait0()  { asm volatile("cp.async.wait_group 0;" ::: "memory"); }
DEVI void cp_wait1()  { asm volatile("cp.async.wait_group 1;" ::: "memory"); }
DEVI void cp_wait2()  { asm volatile("cp.async.wait_group 2;" ::: "memory"); }

DEVI void ldsm4(uint32_t r[4], uint32_t addr) {
    asm volatile("ldmatrix.sync.aligned.m8n8.x4.shared.b16 {%0,%1,%2,%3}, [%4];"
                 : "=r"(r[0]), "=r"(r[1]), "=r"(r[2]), "=r"(r[3]) : "r"(addr));
}
DEVI void mma16816(float d[4], const uint32_t a[4], uint32_t b0, uint32_t b1) {
    asm volatile("mma.sync.aligned.m16n8k16.row.col.f32.f16.f16.f32 "
                 "{%0,%1,%2,%3}, {%4,%5,%6,%7}, {%8,%9}, {%0,%1,%2,%3};"
                 : "+f"(d[0]), "+f"(d[1]), "+f"(d[2]), "+f"(d[3])
                 : "r"(a[0]), "r"(a[1]), "r"(a[2]), "r"(a[3]), "r"(b0), "r"(b1));
}

// pack two fp32 -> f16x2 {lo=lo_f, hi=hi_f}
DEVI uint32_t cvt_f16x2(float hi_f, float lo_f) {
    uint32_t r;
    asm("cvt.rn.f16x2.f32 %0, %1, %2;" : "=r"(r) : "f"(hi_f), "f"(lo_f));
    return r;
}
// w = exp(tanh(s)-1) elementwise on f16x2: ex2( l2e*tanh(s) - l2e )
DEVI uint32_t wfun2(uint32_t s) {
    const uint32_t C  = 0x3DC53DC5u;   // half2(+1.4427)
    const uint32_t NC = 0xBDC5BDC5u;   // half2(-1.4427)
    uint32_t t, u, w;
    asm("tanh.approx.f16x2 %0, %1;" : "=r"(t) : "r"(s));
    asm("fma.rn.f16x2 %0, %1, %2, %3;" : "=r"(u) : "r"(t), "r"(C), "r"(NC));
    asm("ex2.approx.f16x2 %0, %1;" : "=r"(w) : "r"(u));
    return w;
}

DEVI uint32_t h2_as_u32(__half2 h) { uint32_t u; __builtin_memcpy(&u, &h, 4); return u; }

// ---------------- prep: Qf/Kf fp16 feature matrices -------------------------
__global__ void build_qk(const float* __restrict__ e, const float* __restrict__ d,
                         const float* __restrict__ W1, const float* __restrict__ W2) {
    size_t idx = (size_t)blockIdx.x * blockDim.x + threadIdx.x;
    if (idx >= (size_t)B_ * N_ * (F_ / 4)) return;
    int fg = (int)(idx & 63);
    int k  = (int)((idx >> 6) & (N_ - 1));
    int b  = (int)(idx >> 17);
    int f = fg * 4;
    float4 qv, kv;
    if (f < 128) {
        qv = *(const float4*)(W1 + (size_t)k * D_ + f);
        kv = *(const float4*)(e + ((size_t)(b * N_ + k)) * D_ + f);
    } else {
        qv = *(const float4*)(d + ((size_t)(b * N_ + k)) * D_ + (f - 128));
        kv = *(const float4*)(W2 + (size_t)k * D_ + (f - 128));
    }
    __half2 q01 = __floats2half2_rn(qv.x, qv.y), q23 = __floats2half2_rn(qv.z, qv.w);
    __half2 k01 = __floats2half2_rn(kv.x, kv.y), k23 = __floats2half2_rn(kv.z, kv.w);
    *(uint2*)(g_Qf + ((size_t)(b * N_ + k)) * F_ + f) = make_uint2(h2_as_u32(q01), h2_as_u32(q23));
    *(uint2*)(g_Kf + ((size_t)(b * N_ + k)) * F_ + f) = make_uint2(h2_as_u32(k01), h2_as_u32(k23));
}

// ---------------- prep: XT[b,c,m] = fp16(x[b,m,c]) --------------------------
__global__ void transpose_x(const float* __restrict__ x) {
    __shared__ float tile[32][33];
    int b = blockIdx.z;
    int m0 = blockIdx.x * 32, c0 = blockIdx.y * 32;
    int tx = threadIdx.x, ty = threadIdx.y;
#pragma unroll
    for (int i = 0; i < 4; i++)
        tile[ty + 8 * i][tx] = x[((size_t)(b * N_ + m0 + ty + 8 * i)) * D_ + c0 + tx];
    __syncthreads();
#pragma unroll
    for (int i = 0; i < 4; i++)
        g_XT[((size_t)(b * D_ + c0 + ty + 8 * i)) * N_ + m0 + tx] =
            __float2half_rn(tile[tx][ty + 8 * i]);
}

// ---------------- chunk loader: K (64x256) + XT (128x64), swizzled ----------
DEVI void load_chunk(int b, int m0, int stage, uint32_t sb, int tid) {
    const uint32_t stK = sb + SM_K + stage * KSTAGE;
    const uint32_t stX = sb + SM_X + stage * XSTAGE;
    const __half* kbase = g_Kf + ((size_t)(b * N_ + m0)) * F_;
#pragma unroll
    for (int i = 0; i < 8; i++) {
        int lin = tid + i * 256;          // 0..2047
        int row = lin >> 5;               // 0..63
        int ch  = lin & 31;
        cp_async16(stK + row * 512 + ((ch ^ (row & 7)) << 4),
                   kbase + (size_t)row * F_ + ch * 8);
    }
    const __half* xbase = g_XT + (size_t)b * D_ * N_ + m0;
#pragma unroll
    for (int i = 0; i < 4; i++) {
        int lin = tid + i * 256;          // 0..1023
        int row = lin >> 3;               // c: 0..127
        int ch  = lin & 7;
        cp_async16(stX + row * 128 + ((ch ^ (row & 7)) << 4),
                   xbase + (size_t)row * N_ + ch * 8);
    }
    cp_commit();
}

// ---------------- main fused attention kernel -------------------------------
__global__ void __launch_bounds__(256, 1) attn_kernel(float* __restrict__ out) {
    extern __shared__ __align__(1024) char smem[];
    const uint32_t sb = smem_u32(smem);
    const int tid = threadIdx.x;
    const int wid = tid >> 5;
    const int lane = tid & 31;
    const int b = blockIdx.y;
    const int k0 = blockIdx.x * MT;
    const int qb = wid * 32;             // this warp's 32 query rows (2 m-tiles)

    // ---- issue Q (group0), chunk0 (group1), chunk1 (group2) ----
    {
        const __half* qbase = g_Qf + ((size_t)(b * N_ + k0)) * F_;
#pragma unroll
        for (int i = 0; i < 32; i++) {
            int lin = tid + i * 256;      // 0..8191
            int row = lin >> 5;           // 0..255
            int ch  = lin & 31;
            cp_async16(sb + SM_Q + row * 512 + ((ch ^ (row & 7)) << 4),
                       qbase + (size_t)row * F_ + ch * 8);
        }
        cp_commit();
    }
    load_chunk(b, 0, 0, sb, tid);
    load_chunk(b, KT, 1, sb, tid);

    float O[2][16][4];
#pragma unroll
    for (int t = 0; t < 2; t++)
#pragma unroll
        for (int i = 0; i < 16; i++) { O[t][i][0] = O[t][i][1] = O[t][i][2] = O[t][i][3] = 0.f; }
    // denominator accumulators: D-frags of Pf @ ones. d[0]=row g, d[2]=row g+8.
    float den_acc[2][4];
#pragma unroll
    for (int t = 0; t < 2; t++) { den_acc[t][0] = den_acc[t][1] = den_acc[t][2] = den_acc[t][3] = 0.f; }

    // ldmatrix lane maps (verified in R7).
    // A (Q): row = lane&15, col-half = lane>>4.
    // B (K/X): row = (lane&7)+((lane>>4)<<3), col-half = (lane>>3)&1.
    const int arow = lane & 15;
    const int ahi  = lane >> 4;
    const int brow = (lane & 7) + ((lane >> 4) << 3);
    const int bhi  = (lane >> 3) & 1;
    const int xl   = lane & 7;           // row&7 for BOTH maps (tile bases %16==0)
    const uint32_t qrow0 = sb + SM_Q + (qb + arow) * 512;
    const uint32_t qrow1 = qrow0 + 16 * 512;

    cp_wait2();                           // Q group complete
    __syncthreads();

    for (int j = 0; j < NCHUNK; j++) {
        if (j + 1 < NCHUNK) cp_wait1(); else cp_wait0();
        __syncthreads();
        const uint32_t stK = sb + SM_K + (j & 1) * KSTAGE;
        const uint32_t stX = sb + SM_X + (j & 1) * XSTAGE;
        const uint32_t krow = stK + brow * 512;
        const uint32_t xrow = stX + brow * 128;

        // ---- QK: S[32 x 64] = Q @ Kchunk^T (2 m-tiles share every K frag) ----
        float S[2][8][4];
#pragma unroll
        for (int t = 0; t < 2; t++)
#pragma unroll
            for (int i = 0; i < 8; i++) { S[t][i][0] = S[t][i][1] = S[t][i][2] = S[t][i][3] = 0.f; }

#pragma unroll
        for (int kt = 0; kt < 16; kt++) {
            const uint32_t cswA = (uint32_t)(((kt * 2 + ahi) ^ xl) << 4);
            const uint32_t cswB = (uint32_t)(((kt * 2 + bhi) ^ xl) << 4);
            uint32_t qa0[4], qa1[4];
            ldsm4(qa0, qrow0 + cswA);
            ldsm4(qa1, qrow1 + cswA);
#pragma unroll
            for (int ng = 0; ng < 4; ng++) {
                uint32_t kb[4];
                ldsm4(kb, krow + ng * 16 * 512 + cswB);
                mma16816(S[0][2 * ng],     qa0, kb[0], kb[1]);
                mma16816(S[0][2 * ng + 1], qa0, kb[2], kb[3]);
                mma16816(S[1][2 * ng],     qa1, kb[0], kb[1]);
                mma16816(S[1][2 * ng + 1], qa1, kb[2], kb[3]);
            }
        }

        // ---- per t2-group: f16x2 weights -> den ones-MMA -> PV mma ----
#pragma unroll
        for (int t2 = 0; t2 < 4; t2++) {
            uint32_t Pf[2][4];
#pragma unroll
            for (int t = 0; t < 2; t++) {
                int j0 = 2 * t2, j1 = 2 * t2 + 1;
                // pack raw scores to f16x2, then w = ex2(l2e*tanh(s)-l2e)
                Pf[t][0] = wfun2(cvt_f16x2(S[t][j0][1], S[t][j0][0]));  // row g,   k0-7
                Pf[t][1] = wfun2(cvt_f16x2(S[t][j0][3], S[t][j0][2]));  // row g+8, k0-7
                Pf[t][2] = wfun2(cvt_f16x2(S[t][j1][1], S[t][j1][0]));  // row g,   k8-15
                Pf[t][3] = wfun2(cvt_f16x2(S[t][j1][3], S[t][j1][2]));  // row g+8, k8-15
                // denominator: row sums of the SAME fp16 weights
                mma16816(den_acc[t], Pf[t], ONES_H2, ONES_H2);
            }
            const uint32_t cswB = (uint32_t)(((t2 * 2 + bhi) ^ xl) << 4);
#pragma unroll
            for (int cc = 0; cc < 8; cc++) {
                uint32_t xb[4];
                ldsm4(xb, xrow + cc * 16 * 128 + cswB);
                mma16816(O[0][2 * cc],     Pf[0], xb[0], xb[1]);
                mma16816(O[0][2 * cc + 1], Pf[0], xb[2], xb[3]);
                mma16816(O[1][2 * cc],     Pf[1], xb[0], xb[1]);
                mma16816(O[1][2 * cc + 1], Pf[1], xb[2], xb[3]);
            }
        }

        __syncthreads();                  // all warps done with stage (j&1)
        if (j + 2 < NCHUNK) load_chunk(b, (j + 2) * KT, j & 1, sb, tid);
    }

    // ---- epilogue: scale by 1/den (den replicated across quad lanes) ----
#pragma unroll
    for (int t = 0; t < 2; t++) {
        float inv0 = 1.0f / den_acc[t][0];   // row g
        float inv1 = 1.0f / den_acc[t][2];   // row g+8

        int r0 = k0 + qb + t * 16 + (lane >> 2);
        int r1 = r0 + 8;
        float* o0 = out + ((size_t)(b * N_ + r0)) * D_ + (lane & 3) * 2;
        float* o1 = out + ((size_t)(b * N_ + r1)) * D_ + (lane & 3) * 2;
#pragma unroll
        for (int nt = 0; nt < 16; nt++) {
            *(float2*)(o0 + nt * 8) = make_float2(O[t][nt][0] * inv0, O[t][nt][1] * inv0);
            *(float2*)(o1 + nt * 8) = make_float2(O[t][nt][2] * inv1, O[t][nt][3] * inv1);
        }
    }
}

// ---------------- launch ----------------------------------------------------
extern "C" void kernel_launch(void* const* d_in, const int* in_sizes, int n_in,
                              void* d_out, int out_size) {
    const float* x  = (const float*)d_in[0];
    const float* e  = (const float*)d_in[1];
    const float* d  = (const float*)d_in[2];
    const float* W1 = (const float*)d_in[3];
    const float* W2 = (const float*)d_in[4];
    float* out = (float*)d_out;

    cudaFuncSetAttribute(attn_kernel, cudaFuncAttributeMaxDynamicSharedMemorySize, SMEM_TOTAL);

    int threads = 256;
    int blocks = (int)(((size_t)B_ * N_ * (F_ / 4) + threads - 1) / threads);
    build_qk<<<blocks, threads>>>(e, d, W1, W2);

    dim3 tg(N_ / 32, D_ / 32, B_);
    transpose_x<<<tg, dim3(32, 8)>>>(x);

    attn_kernel<<<dim3(N_ / MT, B_), 256, SMEM_TOTAL>>>(out);
}